// round 10
// baseline (speedup 1.0000x reference)
#include <cuda_runtime.h>
#include <cstring>

#define BB 128
#define TT 512
#define II 128
#define HH 256

__device__ float g_xp[(size_t)BB * TT * HH];   // [B][T][H] fp32 scratch (fits L2)

// Packed fp32x2 FMA (sm_103a).
__device__ __forceinline__ float2 ffma2(float2 a, float2 b, float2 c) {
    unsigned long long ua, ub, uc, ud;
    memcpy(&ua, &a, 8); memcpy(&ub, &b, 8); memcpy(&uc, &c, 8);
    asm("fma.rn.f32x2 %0, %1, %2, %3;" : "=l"(ud) : "l"(ua), "l"(ub), "l"(uc));
    float2 d; memcpy(&d, &ud, 8); return d;
}

// Safe fast tanh: e = exp(-2|x|) in (0,1] -> no overflow; validated rel_err 6e-8.
__device__ __forceinline__ float fast_tanh(float x) {
    float e = __expf(-2.0f * fabsf(x));
    float r = __fdividef(1.0f - e, 1.0f + e);
    return copysignf(r, x);
}

// ---------------------------------------------------------------------------
// Phase 1: xp[r,h] = x[r,:] . W_ih[h,:] + (b_ih[h] + b_hh[h])
// PARITY-PAIR LAYOUT (same recipe as the scan): 128 CTAs x 512 threads
// (16 warps, 4/SMSP). Warp w, lane l -> feature j = w*16 + (l>>1), p = l&1.
// Thread holds W_ih float4 indices {2qq+p} (16 f4 = 64 regs). x rows staged
// in SMEM (double-buffered); each h-load presents X and X+16 (one 128B
// segment -> 1 wf). shfl.xor(1) combines the two parity half-dots.
// ---------------------------------------------------------------------------
__global__ void __launch_bounds__(512, 1)
rnn_xproj(const float* __restrict__ x,
          const float* __restrict__ W_ih,
          const float* __restrict__ b_ih,
          const float* __restrict__ b_hh) {
    __shared__ float xs[2][8 * II];               // 2 x 4 KB (8 rows/tile)

    const int tid  = threadIdx.x;
    const int lane = tid & 31;
    const int w    = tid >> 5;
    const int j    = (w << 4) | (lane >> 1);      // feature 0..255
    const int p    = lane & 1;

    const float4* Wi4 = (const float4*)W_ih;      // row j = Wi4[j*32 .. +31]
    float4 wreg[16];
#pragma unroll
    for (int qq = 0; qq < 16; qq++) wreg[qq] = Wi4[j * 32 + 2 * qq + p];

    const float bias = b_ih[j] + b_hh[j];
    const size_t base_row = (size_t)blockIdx.x * 512;

    // preload tile 0 (256 float4; threads 0..255 load one each)
    if (tid < 256)
        ((float4*)xs[0])[tid] = ((const float4*)(x + base_row * II))[tid];
    __syncthreads();

    for (int tile = 0; tile < 64; tile++) {
        const int cur = tile & 1;
        if (tile < 63 && tid < 256) {
            ((float4*)xs[cur ^ 1])[tid] =
                ((const float4*)(x + (base_row + (size_t)(tile + 1) * 8) * II))[tid];
        }

        const size_t r0 = base_row + (size_t)tile * 8;
#pragma unroll
        for (int r = 0; r < 8; r++) {
            const float4* xr = (const float4*)(xs[cur] + r * II);
            float2 a0 = make_float2(0.0f, 0.0f), a1 = a0, a2 = a0, a3 = a0;
#pragma unroll
            for (int qq = 0; qq < 16; qq++) {
                float4 xv = xr[2 * qq + p];
                if (qq & 1) {
                    a2 = ffma2(make_float2(xv.x, xv.y), make_float2(wreg[qq].x, wreg[qq].y), a2);
                    a3 = ffma2(make_float2(xv.z, xv.w), make_float2(wreg[qq].z, wreg[qq].w), a3);
                } else {
                    a0 = ffma2(make_float2(xv.x, xv.y), make_float2(wreg[qq].x, wreg[qq].y), a0);
                    a1 = ffma2(make_float2(xv.z, xv.w), make_float2(wreg[qq].z, wreg[qq].w), a1);
                }
            }
            float dot = ((a0.x + a0.y) + (a1.x + a1.y)) +
                        ((a2.x + a2.y) + (a3.x + a3.y));
            dot += __shfl_xor_sync(0xffffffffu, dot, 1);   // combine parities
            if (p == 0)
                g_xp[(r0 + r) * HH + j] = dot + bias;      // 16 consec floats/warp
        }
        __syncthreads();
    }
}

// ---------------------------------------------------------------------------
// Phase 2 + 3: recurrent scan — UNCHANGED from R8 (validated 489 us).
// PARITY-PAIR LAYOUT: warp w, lane l -> feature j = w*16 + (l>>1), p = l&1.
// Thread (j,p) takes W/h float4 indices {2*qq + p}, qq=0..31.
//   - every h LDS.128 presents X and X+16 (same 128B segment) -> 1 wf.
//   - partial exchange = shfl.xor(1); ONE __syncthreads per step.
//   - W: qq<NREG in regs; tail in SMEM [qq][j*2+p].
// ---------------------------------------------------------------------------
#define NREG 22
#define NTAIL 10

__global__ void __launch_bounds__(512, 1)
rnn_scan(const float* __restrict__ W_hh,
         const float* __restrict__ W_fc,
         const float* __restrict__ b_fc,
         float* __restrict__ out) {
    extern __shared__ float sm[];
    float4* wt4 = (float4*)sm;                  // [NTAIL][512] float4 = 80 KB
    float*  hA  = sm + NTAIL * 512 * 4;         // 256 floats
    float*  hB  = hA + HH;                      // 256 floats
    float*  red = hB + HH;                      // 8 floats

    const int tid  = threadIdx.x;
    const int lane = tid & 31;
    const int w    = tid >> 5;
    const int j    = (w << 4) | (lane >> 1);    // 0..255
    const int p    = lane & 1;
    const int b    = blockIdx.x;

    const float4* W4 = (const float4*)W_hh;     // row j = W4[j*64 .. +63]

    float4 wreg[NREG];
#pragma unroll
    for (int qq = 0; qq < NREG; qq++) wreg[qq] = W4[j * 64 + 2 * qq + p];

#pragma unroll
    for (int qq = 0; qq < NTAIL; qq++)
        wt4[qq * 512 + j * 2 + p] = W4[j * 64 + 2 * (NREG + qq) + p];

    if (tid < HH) { hA[tid] = 0.0f; hB[tid] = 0.0f; }
    __syncthreads();

    const float*  xp  = g_xp + (size_t)b * TT * HH + j;
    const float4* wtp = wt4 + j * 2 + p;        // wtp[qq*512]

    float* hcur = hA;
    float* hnxt = hB;

    for (int t = 0; t < TT; t++) {
        const float xpv = xp[(size_t)t * HH];   // early issue, L2-hit

        const float4* hs4 = (const float4*)hcur;
        float2 a0 = make_float2(0.0f, 0.0f), a1 = a0, a2 = a0, a3 = a0;

        // SMEM W-tail first: LDS latency overlaps the register-W FMA stream
#pragma unroll
        for (int qq = 0; qq < NTAIL; qq++) {
            float4 h4 = hs4[2 * (NREG + qq) + p];
            float4 w4 = wtp[qq * 512];
            if (qq & 1) {
                a2 = ffma2(make_float2(h4.x, h4.y), make_float2(w4.x, w4.y), a2);
                a3 = ffma2(make_float2(h4.z, h4.w), make_float2(w4.z, w4.w), a3);
            } else {
                a0 = ffma2(make_float2(h4.x, h4.y), make_float2(w4.x, w4.y), a0);
                a1 = ffma2(make_float2(h4.z, h4.w), make_float2(w4.z, w4.w), a1);
            }
        }
#pragma unroll
        for (int qq = 0; qq < NREG; qq++) {
            float4 h4 = hs4[2 * qq + p];
            if (qq & 1) {
                a2 = ffma2(make_float2(h4.x, h4.y), make_float2(wreg[qq].x, wreg[qq].y), a2);
                a3 = ffma2(make_float2(h4.z, h4.w), make_float2(wreg[qq].z, wreg[qq].w), a3);
            } else {
                a0 = ffma2(make_float2(h4.x, h4.y), make_float2(wreg[qq].x, wreg[qq].y), a0);
                a1 = ffma2(make_float2(h4.z, h4.w), make_float2(wreg[qq].z, wreg[qq].w), a1);
            }
        }

        const float mydot = ((a0.x + a0.y) + (a1.x + a1.y)) +
                            ((a2.x + a2.y) + (a3.x + a3.y));

        // in-warp exchange of the two parity partials (no SMEM, no extra bar)
        const float other = __shfl_xor_sync(0xffffffffu, mydot, 1);
        const float hn = fast_tanh(xpv + mydot + other);  // identical in pair

        if (p == 0) hnxt[j] = hn;               // even lanes publish (16 consec/warp)
        __syncthreads();                        // single barrier: h published

        float* tmp = hcur; hcur = hnxt; hnxt = tmp;
    }

    // Phase 3: out[b] = sigmoid(h . W_fc + b_fc)  (first 256 threads)
    if (tid < HH) {
        float v = hcur[tid] * W_fc[tid];
#pragma unroll
        for (int o = 16; o > 0; o >>= 1) v += __shfl_down_sync(0xffffffffu, v, o);
        if ((tid & 31) == 0) red[tid >> 5] = v;
    }
    __syncthreads();
    if (tid == 0) {
        float s = b_fc[0];
#pragma unroll
        for (int w2 = 0; w2 < 8; w2++) s += red[w2];
        out[b] = 1.0f / (1.0f + expf(-s));
    }
}

// ---------------------------------------------------------------------------

extern "C" void kernel_launch(void* const* d_in, const int* in_sizes, int n_in,
                              void* d_out, int out_size) {
    const float* x    = (const float*)d_in[0];
    const float* W_ih = (const float*)d_in[1];
    const float* W_hh = (const float*)d_in[2];
    const float* b_ih = (const float*)d_in[3];
    const float* b_hh = (const float*)d_in[4];
    const float* W_fc = (const float*)d_in[5];
    const float* b_fc = (const float*)d_in[6];
    float* out = (float*)d_out;

    const int smem_b = (NTAIL * 512 * 4 + 2 * HH + 8) * (int)sizeof(float); // ~84 KB
    cudaFuncSetAttribute(rnn_scan, cudaFuncAttributeMaxDynamicSharedMemorySize, smem_b);

    rnn_xproj<<<128, 512>>>(x, W_ih, b_ih, b_hh);
    rnn_scan<<<BB, 512, smem_b>>>(W_hh, W_fc, b_fc, out);
}

// round 11
// speedup vs baseline: 1.6250x; 1.6250x over previous
#include <cuda_runtime.h>
#include <cstring>

#define BB 128
#define TT 512
#define II 128
#define HH 256

__device__ float g_xp[(size_t)BB * TT * HH];   // [B][T][H] fp32 scratch (fits L2)

// Packed fp32x2 FMA (sm_103a).
__device__ __forceinline__ float2 ffma2(float2 a, float2 b, float2 c) {
    unsigned long long ua, ub, uc, ud;
    memcpy(&ua, &a, 8); memcpy(&ub, &b, 8); memcpy(&uc, &c, 8);
    asm("fma.rn.f32x2 %0, %1, %2, %3;" : "=l"(ud) : "l"(ua), "l"(ub), "l"(uc));
    float2 d; memcpy(&d, &ud, 8); return d;
}

// Safe fast tanh: e = exp(-2|x|) in (0,1] -> no overflow; validated rel_err 6e-8.
__device__ __forceinline__ float fast_tanh(float x) {
    float e = __expf(-2.0f * fabsf(x));
    float r = __fdividef(1.0f - e, 1.0f + e);
    return copysignf(r, x);
}

// ---------------------------------------------------------------------------
// Phase 1: xp[r,h] = x[r,:] . W_ih[h,:] + (b_ih[h] + b_hh[h])
// PARITY-PAIR LAYOUT: 128 CTAs x 512 threads (16 warps, 4/SMSP).
// Warp w, lane l -> feature j = w*16 + (l>>1), p = l&1. Thread holds W_ih
// float4 indices {2qq+p} (16 f4 = 64 regs). x tiles double-buffered in SMEM;
// each x-load presents X and X+16 (one 128B segment -> 1 wf). shfl.xor(1)
// combines the parity half-dots.
// ---------------------------------------------------------------------------
__global__ void __launch_bounds__(512, 1)
rnn_xproj(const float* __restrict__ x,
          const float* __restrict__ W_ih,
          const float* __restrict__ b_ih,
          const float* __restrict__ b_hh) {
    __shared__ float xs[2][8 * II];               // 2 x 4 KB (8 rows/tile)

    const int tid  = threadIdx.x;
    const int lane = tid & 31;
    const int w    = tid >> 5;
    const int j    = (w << 4) | (lane >> 1);      // feature 0..255
    const int p    = lane & 1;

    const float4* Wi4 = (const float4*)W_ih;      // row j = Wi4[j*32 .. +31]
    float4 wreg[16];
#pragma unroll
    for (int qq = 0; qq < 16; qq++) wreg[qq] = Wi4[j * 32 + 2 * qq + p];

    const float bias = b_ih[j] + b_hh[j];
    const size_t base_row = (size_t)blockIdx.x * 512;

    if (tid < 256)
        ((float4*)xs[0])[tid] = ((const float4*)(x + base_row * II))[tid];
    __syncthreads();

    for (int tile = 0; tile < 64; tile++) {
        const int cur = tile & 1;
        if (tile < 63 && tid < 256) {
            ((float4*)xs[cur ^ 1])[tid] =
                ((const float4*)(x + (base_row + (size_t)(tile + 1) * 8) * II))[tid];
        }

        const size_t r0 = base_row + (size_t)tile * 8;
#pragma unroll
        for (int r = 0; r < 8; r++) {
            const float4* xr = (const float4*)(xs[cur] + r * II);
            float2 a0 = make_float2(0.0f, 0.0f), a1 = a0, a2 = a0, a3 = a0;
#pragma unroll
            for (int qq = 0; qq < 16; qq++) {
                float4 xv = xr[2 * qq + p];
                if (qq & 1) {
                    a2 = ffma2(make_float2(xv.x, xv.y), make_float2(wreg[qq].x, wreg[qq].y), a2);
                    a3 = ffma2(make_float2(xv.z, xv.w), make_float2(wreg[qq].z, wreg[qq].w), a3);
                } else {
                    a0 = ffma2(make_float2(xv.x, xv.y), make_float2(wreg[qq].x, wreg[qq].y), a0);
                    a1 = ffma2(make_float2(xv.z, xv.w), make_float2(wreg[qq].z, wreg[qq].w), a1);
                }
            }
            float dot = ((a0.x + a0.y) + (a1.x + a1.y)) +
                        ((a2.x + a2.y) + (a3.x + a3.y));
            dot += __shfl_xor_sync(0xffffffffu, dot, 1);   // combine parities
            if (p == 0)
                g_xp[(r0 + r) * HH + j] = dot + bias;      // 16 consec floats/warp
        }
        __syncthreads();
    }
}

// ---------------------------------------------------------------------------
// Phase 2 + 3: recurrent scan — R8 structure (validated 489 us at healthy
// clocks) + xp software pipeline (prefetch xp[t+1] during step t's dot).
// PARITY-PAIR LAYOUT: warp w, lane l -> feature j = w*16 + (l>>1), p = l&1.
// Thread (j,p) takes W/h float4 indices {2*qq + p}, qq=0..31.
//   - every h LDS.128 presents X and X+16 (same 128B segment) -> 1 wf.
//   - partial exchange = shfl.xor(1); ONE __syncthreads per step.
//   - W: qq<NREG in regs; tail in SMEM [qq][j*2+p].
// ---------------------------------------------------------------------------
#define NREG 22
#define NTAIL 10

__global__ void __launch_bounds__(512, 1)
rnn_scan(const float* __restrict__ W_hh,
         const float* __restrict__ W_fc,
         const float* __restrict__ b_fc,
         float* __restrict__ out) {
    extern __shared__ float sm[];
    float4* wt4 = (float4*)sm;                  // [NTAIL][512] float4 = 80 KB
    float*  hA  = sm + NTAIL * 512 * 4;         // 256 floats
    float*  hB  = hA + HH;                      // 256 floats
    float*  red = hB + HH;                      // 8 floats

    const int tid  = threadIdx.x;
    const int lane = tid & 31;
    const int w    = tid >> 5;
    const int j    = (w << 4) | (lane >> 1);    // 0..255
    const int p    = lane & 1;
    const int b    = blockIdx.x;

    const float4* W4 = (const float4*)W_hh;     // row j = W4[j*64 .. +63]

    float4 wreg[NREG];
#pragma unroll
    for (int qq = 0; qq < NREG; qq++) wreg[qq] = W4[j * 64 + 2 * qq + p];

#pragma unroll
    for (int qq = 0; qq < NTAIL; qq++)
        wt4[qq * 512 + j * 2 + p] = W4[j * 64 + 2 * (NREG + qq) + p];

    if (tid < HH) { hA[tid] = 0.0f; hB[tid] = 0.0f; }
    __syncthreads();

    const float*  xp  = g_xp + (size_t)b * TT * HH + j;
    const float4* wtp = wt4 + j * 2 + p;        // wtp[qq*512]

    float* hcur = hA;
    float* hnxt = hB;

    float xpv = xp[0];                          // pipeline head

    for (int t = 0; t < TT; t++) {
        const float4* hs4 = (const float4*)hcur;
        float2 a0 = make_float2(0.0f, 0.0f), a1 = a0, a2 = a0, a3 = a0;

        // SMEM W-tail first: LDS latency overlaps the register-W FMA stream
#pragma unroll
        for (int qq = 0; qq < NTAIL; qq++) {
            float4 h4 = hs4[2 * (NREG + qq) + p];
            float4 w4 = wtp[qq * 512];
            if (qq & 1) {
                a2 = ffma2(make_float2(h4.x, h4.y), make_float2(w4.x, w4.y), a2);
                a3 = ffma2(make_float2(h4.z, h4.w), make_float2(w4.z, w4.w), a3);
            } else {
                a0 = ffma2(make_float2(h4.x, h4.y), make_float2(w4.x, w4.y), a0);
                a1 = ffma2(make_float2(h4.z, h4.w), make_float2(w4.z, w4.w), a1);
            }
        }
#pragma unroll
        for (int qq = 0; qq < NREG; qq++) {
            float4 h4 = hs4[2 * qq + p];
            if (qq & 1) {
                a2 = ffma2(make_float2(h4.x, h4.y), make_float2(wreg[qq].x, wreg[qq].y), a2);
                a3 = ffma2(make_float2(h4.z, h4.w), make_float2(wreg[qq].z, wreg[qq].w), a3);
            } else {
                a0 = ffma2(make_float2(h4.x, h4.y), make_float2(wreg[qq].x, wreg[qq].y), a0);
                a1 = ffma2(make_float2(h4.z, h4.w), make_float2(wreg[qq].z, wreg[qq].w), a1);
            }
        }

        // prefetch next step's xp while the dot's exchange/tanh drains
        float xpn = 0.0f;
        if (t + 1 < TT) xpn = xp[(size_t)(t + 1) * HH];

        const float mydot = ((a0.x + a0.y) + (a1.x + a1.y)) +
                            ((a2.x + a2.y) + (a3.x + a3.y));

        // in-warp exchange of the two parity partials (no SMEM, no extra bar)
        const float other = __shfl_xor_sync(0xffffffffu, mydot, 1);
        const float hn = fast_tanh(xpv + mydot + other);  // identical in pair

        if (p == 0) hnxt[j] = hn;               // even lanes publish (16 consec/warp)
        __syncthreads();                        // single barrier: h published

        xpv = xpn;
        float* tmp = hcur; hcur = hnxt; hnxt = tmp;
    }

    // Phase 3: out[b] = sigmoid(h . W_fc + b_fc)  (first 256 threads)
    if (tid < HH) {
        float v = hcur[tid] * W_fc[tid];
#pragma unroll
        for (int o = 16; o > 0; o >>= 1) v += __shfl_down_sync(0xffffffffu, v, o);
        if ((tid & 31) == 0) red[tid >> 5] = v;
    }
    __syncthreads();
    if (tid == 0) {
        float s = b_fc[0];
#pragma unroll
        for (int w2 = 0; w2 < 8; w2++) s += red[w2];
        out[b] = 1.0f / (1.0f + expf(-s));
    }
}

// ---------------------------------------------------------------------------

extern "C" void kernel_launch(void* const* d_in, const int* in_sizes, int n_in,
                              void* d_out, int out_size) {
    const float* x    = (const float*)d_in[0];
    const float* W_ih = (const float*)d_in[1];
    const float* W_hh = (const float*)d_in[2];
    const float* b_ih = (const float*)d_in[3];
    const float* b_hh = (const float*)d_in[4];
    const float* W_fc = (const float*)d_in[5];
    const float* b_fc = (const float*)d_in[6];
    float* out = (float*)d_out;

    const int smem_b = (NTAIL * 512 * 4 + 2 * HH + 8) * (int)sizeof(float); // ~84 KB
    cudaFuncSetAttribute(rnn_scan, cudaFuncAttributeMaxDynamicSharedMemorySize, smem_b);

    rnn_xproj<<<128, 512>>>(x, W_ih, b_ih, b_hh);
    rnn_scan<<<BB, 512, smem_b>>>(W_hh, W_fc, b_fc, out);
}

// round 12
// speedup vs baseline: 1.8548x; 1.1414x over previous
#include <cuda_runtime.h>
#include <cuda_bf16.h>
#include <cstring>

#define BB 128
#define TT 512
#define II 128
#define HH 256

__device__ float g_xp[(size_t)BB * TT * HH];   // [B][T][H] fp32 scratch (fits L2)

// Packed fp32x2 FMA (sm_103a).
__device__ __forceinline__ float2 ffma2(float2 a, float2 b, float2 c) {
    unsigned long long ua, ub, uc, ud;
    memcpy(&ua, &a, 8); memcpy(&ub, &b, 8); memcpy(&uc, &c, 8);
    asm("fma.rn.f32x2 %0, %1, %2, %3;" : "=l"(ud) : "l"(ua), "l"(ub), "l"(uc));
    float2 d; memcpy(&d, &ud, 8); return d;
}

// Safe fast tanh: e = exp(-2|x|) in (0,1] -> no overflow; validated rel_err 6e-8.
__device__ __forceinline__ float fast_tanh(float x) {
    float e = __expf(-2.0f * fabsf(x));
    float r = __fdividef(1.0f - e, 1.0f + e);
    return copysignf(r, x);
}

// Two packed bf16 -> two exact fp32 (bit ops on the idle ALU pipe).
__device__ __forceinline__ float2 bf2_to_f2(unsigned u) {
    float2 r;
    r.x = __uint_as_float(u << 16);
    r.y = __uint_as_float(u & 0xFFFF0000u);
    return r;
}

// Pack two fp32 -> one u32 of bf16 (round-to-nearest), lo in low half.
__device__ __forceinline__ unsigned f2_to_bf2(float a, float b) {
    unsigned short ua = __bfloat16_as_ushort(__float2bfloat16_rn(a));
    unsigned short ub = __bfloat16_as_ushort(__float2bfloat16_rn(b));
    return (unsigned)ua | ((unsigned)ub << 16);
}

// ---------------------------------------------------------------------------
// Phase 1: xp[r,h] = x[r,:] . W_ih[h,:] + (b_ih[h] + b_hh[h])
// PARITY-PAIR LAYOUT: 128 CTAs x 512 threads (16 warps, 4/SMSP).
// ---------------------------------------------------------------------------
__global__ void __launch_bounds__(512, 1)
rnn_xproj(const float* __restrict__ x,
          const float* __restrict__ W_ih,
          const float* __restrict__ b_ih,
          const float* __restrict__ b_hh) {
    __shared__ float xs[2][8 * II];               // 2 x 4 KB (8 rows/tile)

    const int tid  = threadIdx.x;
    const int lane = tid & 31;
    const int w    = tid >> 5;
    const int j    = (w << 4) | (lane >> 1);      // feature 0..255
    const int p    = lane & 1;

    const float4* Wi4 = (const float4*)W_ih;      // row j = Wi4[j*32 .. +31]
    float4 wreg[16];
#pragma unroll
    for (int qq = 0; qq < 16; qq++) wreg[qq] = Wi4[j * 32 + 2 * qq + p];

    const float bias = b_ih[j] + b_hh[j];
    const size_t base_row = (size_t)blockIdx.x * 512;

    if (tid < 256)
        ((float4*)xs[0])[tid] = ((const float4*)(x + base_row * II))[tid];
    __syncthreads();

    for (int tile = 0; tile < 64; tile++) {
        const int cur = tile & 1;
        if (tile < 63 && tid < 256) {
            ((float4*)xs[cur ^ 1])[tid] =
                ((const float4*)(x + (base_row + (size_t)(tile + 1) * 8) * II))[tid];
        }

        const size_t r0 = base_row + (size_t)tile * 8;
#pragma unroll
        for (int r = 0; r < 8; r++) {
            const float4* xr = (const float4*)(xs[cur] + r * II);
            float2 a0 = make_float2(0.0f, 0.0f), a1 = a0, a2 = a0, a3 = a0;
#pragma unroll
            for (int qq = 0; qq < 16; qq++) {
                float4 xv = xr[2 * qq + p];
                if (qq & 1) {
                    a2 = ffma2(make_float2(xv.x, xv.y), make_float2(wreg[qq].x, wreg[qq].y), a2);
                    a3 = ffma2(make_float2(xv.z, xv.w), make_float2(wreg[qq].z, wreg[qq].w), a3);
                } else {
                    a0 = ffma2(make_float2(xv.x, xv.y), make_float2(wreg[qq].x, wreg[qq].y), a0);
                    a1 = ffma2(make_float2(xv.z, xv.w), make_float2(wreg[qq].z, wreg[qq].w), a1);
                }
            }
            float dot = ((a0.x + a0.y) + (a1.x + a1.y)) +
                        ((a2.x + a2.y) + (a3.x + a3.y));
            dot += __shfl_xor_sync(0xffffffffu, dot, 1);   // combine parities
            if (p == 0)
                g_xp[(r0 + r) * HH + j] = dot + bias;      // 16 consec floats/warp
        }
        __syncthreads();
    }
}

// ---------------------------------------------------------------------------
// Phase 2 + 3: recurrent scan — R8/R11 structure + BF16-PACKED W-TAIL.
// PARITY-PAIR LAYOUT: warp w, lane l -> feature j = w*16 + (l>>1), p = l&1.
// Thread (j,p) covers W/h float4 indices {2*qq + p}, qq = 0..31:
//   qq < NREG (=22): W in fp32 registers.
//   qq = 22..31: W packed as bf16 pairs in SMEM — 5 uint4 loads/thread
//     (8 weights each) instead of 10 float4 -> tail crossbar bytes halve
//     (640 -> 320 wf/step). Decompress = shift/mask (exact, ALU pipe).
// h stays fp32 (1 wf per broadcast load). shfl.xor(1) exchange; ONE bar/step.
// ---------------------------------------------------------------------------
#define NREG 22

__global__ void __launch_bounds__(512, 1)
rnn_scan(const float* __restrict__ W_hh,
         const float* __restrict__ W_fc,
         const float* __restrict__ b_fc,
         float* __restrict__ out) {
    extern __shared__ float sm[];
    uint4* wtU = (uint4*)sm;                    // [5][512] uint4 = 40 KB
    float* hA  = sm + 5 * 512 * 4;              // 256 floats
    float* hB  = hA + HH;                       // 256 floats
    float* red = hB + HH;                       // 8 floats

    const int tid  = threadIdx.x;
    const int lane = tid & 31;
    const int w    = tid >> 5;
    const int j    = (w << 4) | (lane >> 1);    // 0..255
    const int p    = lane & 1;
    const int b    = blockIdx.x;

    const float4* W4 = (const float4*)W_hh;     // row j = W4[j*64 .. +63]

    float4 wreg[NREG];
#pragma unroll
    for (int qq = 0; qq < NREG; qq++) wreg[qq] = W4[j * 64 + 2 * qq + p];

    // Pack tail (qq = NREG..31) into bf16 pairs: slot s holds qq=NREG+2s, +2s+1.
#pragma unroll
    for (int s = 0; s < 5; s++) {
        float4 wa = W4[j * 64 + 2 * (NREG + 2 * s) + p];
        float4 wb = W4[j * 64 + 2 * (NREG + 2 * s + 1) + p];
        uint4 u;
        u.x = f2_to_bf2(wa.x, wa.y);
        u.y = f2_to_bf2(wa.z, wa.w);
        u.z = f2_to_bf2(wb.x, wb.y);
        u.w = f2_to_bf2(wb.z, wb.w);
        wtU[s * 512 + j * 2 + p] = u;
    }

    if (tid < HH) { hA[tid] = 0.0f; hB[tid] = 0.0f; }
    __syncthreads();

    const float* xp  = g_xp + (size_t)b * TT * HH + j;
    const uint4* wtp = wtU + j * 2 + p;         // wtp[s*512]

    float* hcur = hA;
    float* hnxt = hB;

    float xpv = xp[0];                          // pipeline head

    for (int t = 0; t < TT; t++) {
        const float4* hs4 = (const float4*)hcur;
        float2 a0 = make_float2(0.0f, 0.0f), a1 = a0, a2 = a0, a3 = a0;

        // bf16 W-tail first: LDS latency overlaps the register-W FMA stream
#pragma unroll
        for (int s = 0; s < 5; s++) {
            uint4 wv = wtp[s * 512];
            float4 ha = hs4[2 * (NREG + 2 * s) + p];
            float4 hb = hs4[2 * (NREG + 2 * s + 1) + p];
            a0 = ffma2(make_float2(ha.x, ha.y), bf2_to_f2(wv.x), a0);
            a1 = ffma2(make_float2(ha.z, ha.w), bf2_to_f2(wv.y), a1);
            a2 = ffma2(make_float2(hb.x, hb.y), bf2_to_f2(wv.z), a2);
            a3 = ffma2(make_float2(hb.z, hb.w), bf2_to_f2(wv.w), a3);
        }
#pragma unroll
        for (int qq = 0; qq < NREG; qq++) {
            float4 h4 = hs4[2 * qq + p];
            if (qq & 1) {
                a2 = ffma2(make_float2(h4.x, h4.y), make_float2(wreg[qq].x, wreg[qq].y), a2);
                a3 = ffma2(make_float2(h4.z, h4.w), make_float2(wreg[qq].z, wreg[qq].w), a3);
            } else {
                a0 = ffma2(make_float2(h4.x, h4.y), make_float2(wreg[qq].x, wreg[qq].y), a0);
                a1 = ffma2(make_float2(h4.z, h4.w), make_float2(wreg[qq].z, wreg[qq].w), a1);
            }
        }

        // prefetch next step's xp while the exchange/tanh drains
        float xpn = 0.0f;
        if (t + 1 < TT) xpn = xp[(size_t)(t + 1) * HH];

        const float mydot = ((a0.x + a0.y) + (a1.x + a1.y)) +
                            ((a2.x + a2.y) + (a3.x + a3.y));

        const float other = __shfl_xor_sync(0xffffffffu, mydot, 1);
        const float hn = fast_tanh(xpv + mydot + other);  // identical in pair

        if (p == 0) hnxt[j] = hn;               // even lanes publish
        __syncthreads();                        // single barrier per step

        xpv = xpn;
        float* tmp = hcur; hcur = hnxt; hnxt = tmp;
    }

    // Phase 3: out[b] = sigmoid(h . W_fc + b_fc)
    if (tid < HH) {
        float v = hcur[tid] * W_fc[tid];
#pragma unroll
        for (int o = 16; o > 0; o >>= 1) v += __shfl_down_sync(0xffffffffu, v, o);
        if ((tid & 31) == 0) red[tid >> 5] = v;
    }
    __syncthreads();
    if (tid == 0) {
        float s = b_fc[0];
#pragma unroll
        for (int w2 = 0; w2 < 8; w2++) s += red[w2];
        out[b] = 1.0f / (1.0f + expf(-s));
    }
}

// ---------------------------------------------------------------------------

extern "C" void kernel_launch(void* const* d_in, const int* in_sizes, int n_in,
                              void* d_out, int out_size) {
    const float* x    = (const float*)d_in[0];
    const float* W_ih = (const float*)d_in[1];
    const float* W_hh = (const float*)d_in[2];
    const float* b_ih = (const float*)d_in[3];
    const float* b_hh = (const float*)d_in[4];
    const float* W_fc = (const float*)d_in[5];
    const float* b_fc = (const float*)d_in[6];
    float* out = (float*)d_out;

    const int smem_b = (5 * 512 * 4 + 2 * HH + 8) * (int)sizeof(float);  // ~42 KB
    cudaFuncSetAttribute(rnn_scan, cudaFuncAttributeMaxDynamicSharedMemorySize, smem_b);

    rnn_xproj<<<128, 512>>>(x, W_ih, b_ih, b_hh);
    rnn_scan<<<BB, 512, smem_b>>>(W_hh, W_fc, b_fc, out);
}